// round 9
// baseline (speedup 1.0000x reference)
#include <cuda_runtime.h>
#include <cuda_bf16.h>
#include <math.h>
#include <stdint.h>

#define NA   32
#define LA   32
#define BB   64
#define LBD  32
#define DIN  768
#define HD   768
#define MQ   (NA*LA)     // 1024
#define MKV  (BB*LBD)    // 2048
#define OT_INV_EPS 10.0f
#define INV768 (1.0f/768.0f)

typedef unsigned long long u64;
typedef __nv_bfloat16 bf16;

// ---------------- scratch (device globals; no allocation allowed) ----------
__device__ float g_q[MQ*HD];
__device__ float g_k[MKV*HD];
__device__ float g_v[MKV*HD];
__device__ float g_ecls[NA*HD];
__device__ float g_qinv[MQ];
__device__ float g_kinv[MKV];
__device__ float g_Tp[MQ*MKV];      // sinkhorn output, tile-packed
__device__ float g_Mp[MQ*MKV];      // M = q@v^T, tile-packed
// per-row / per-pair small stats
__device__ float g_qsum[MQ], g_qsq[MQ], g_qwsp[MQ];
__device__ float g_G[BB*1024];      // Gram v_b v_b^T
__device__ float g_vsum[BB*32], g_vwsp[BB*32];
__device__ float g_S1;
__device__ float g_WR[MQ*BB/16*32]; // actually 2048*32
__device__ float g_C[2048*32];
__device__ float g_K[2048];
__device__ float g_R[2048*HD];      // 6 MB pooled-raw
// bf16 hi/lo operands
__device__ __align__(16) bf16 g_qh[MQ*HD];
__device__ __align__(16) bf16 g_ql[MQ*HD];
__device__ __align__(16) bf16 g_kh[MKV*HD];
__device__ __align__(16) bf16 g_kl[MKV*HD];
__device__ __align__(16) bf16 g_vh[MKV*HD];
__device__ __align__(16) bf16 g_vl[MKV*HD];
__device__ __align__(16) bf16 g_eth[MQ*DIN],  g_etl[MQ*DIN];
__device__ __align__(16) bf16 g_mth[MKV*DIN], g_mtl[MKV*DIN];
__device__ __align__(16) bf16 g_ech[NA*DIN],  g_ecl[NA*DIN];
__device__ __align__(16) bf16 g_wqh[HD*DIN],  g_wql[HD*DIN];
__device__ __align__(16) bf16 g_wkh[HD*DIN],  g_wkl[HD*DIN];
__device__ __align__(16) bf16 g_wvh[HD*DIN],  g_wvl[HD*DIN];
__device__ __align__(16) bf16 g_wch[HD*DIN],  g_wcl[HD*DIN];

// ---------------- helpers ----------------------------------------------------
__device__ __forceinline__ float warp_sum(float x) {
#pragma unroll
    for (int o = 16; o > 0; o >>= 1) x += __shfl_xor_sync(0xffffffffu, x, o);
    return x;
}
__device__ __forceinline__ float warp_max(float x) {
#pragma unroll
    for (int o = 16; o > 0; o >>= 1) x = fmaxf(x, __shfl_xor_sync(0xffffffffu, x, o));
    return x;
}
__device__ __forceinline__ uint32_t smem_u32(const void* p) {
    uint32_t a;
    asm("{ .reg .u64 t; cvta.to.shared.u64 t, %1; cvt.u32.u64 %0, t; }"
        : "=r"(a) : "l"(p));
    return a;
}
__device__ __forceinline__ void ldsm4(uint32_t* r, uint32_t addr) {
    asm volatile("ldmatrix.sync.aligned.m8n8.x4.shared.b16 {%0,%1,%2,%3}, [%4];"
        : "=r"(r[0]), "=r"(r[1]), "=r"(r[2]), "=r"(r[3]) : "r"(addr));
}
__device__ __forceinline__ void mma_bf16(float* c, const uint32_t* a, const uint32_t* b) {
    asm volatile(
        "mma.sync.aligned.m16n8k16.row.col.f32.bf16.bf16.f32 "
        "{%0,%1,%2,%3}, {%4,%5,%6,%7}, {%8,%9}, {%0,%1,%2,%3};"
        : "+f"(c[0]), "+f"(c[1]), "+f"(c[2]), "+f"(c[3])
        : "r"(a[0]), "r"(a[1]), "r"(a[2]), "r"(a[3]), "r"(b[0]), "r"(b[1]));
}
#define CPA(sm, gm) \
    asm volatile("cp.async.ca.shared.global [%0], [%1], 16;" :: "r"(sm), "l"(gm))
#define CPA_COMMIT() asm volatile("cp.async.commit_group;" ::: "memory")
#define CPA_WAIT(n)  asm volatile("cp.async.wait_group %0;" :: "n"(n) : "memory")

__device__ __forceinline__ void split4(const float4 v, uint2& h, uint2& l) {
    unsigned short hb[4], lb[4];
    const float vv[4] = {v.x, v.y, v.z, v.w};
#pragma unroll
    for (int e = 0; e < 4; e++) {
        bf16 hh = __float2bfloat16(vv[e]);
        bf16 ll = __float2bfloat16(vv[e] - __bfloat162float(hh));
        hb[e] = *(unsigned short*)&hh;
        lb[e] = *(unsigned short*)&ll;
    }
    h.x = (uint32_t)hb[0] | ((uint32_t)hb[1] << 16);
    h.y = (uint32_t)hb[2] | ((uint32_t)hb[3] << 16);
    l.x = (uint32_t)lb[0] | ((uint32_t)lb[1] << 16);
    l.y = (uint32_t)lb[2] | ((uint32_t)lb[3] << 16);
}
__device__ __forceinline__ uint32_t split2(float a, float b, uint32_t& lo) {
    bf16 h0 = __float2bfloat16(a);
    bf16 h1 = __float2bfloat16(b);
    bf16 l0 = __float2bfloat16(a - __bfloat162float(h0));
    bf16 l1 = __float2bfloat16(b - __bfloat162float(h1));
    lo = (uint32_t)(*(unsigned short*)&l0) | ((uint32_t)(*(unsigned short*)&l1) << 16);
    return (uint32_t)(*(unsigned short*)&h0) | ((uint32_t)(*(unsigned short*)&h1) << 16);
}

// ---------------- shared GEMM mainloop (BM=BN=128, BK=32) -------------------
#define TILE_B   10240
#define BUF_B    40960
#define SMEM_MMA (2 * BUF_B)

__device__ __forceinline__ void issue_stage(
    const bf16* Ah, const bf16* Al, const bf16* Bh, const bf16* Bl,
    int aRow0, int aMax, int bRow0, uint32_t sbase, int k0, int buf, int tid)
{
#pragma unroll
    for (int i = 0; i < 8; i++) {
        const int c = tid + i * 256;
        const int tile = c >> 9, cc = c & 511, row = cc >> 2, ch = cc & 3;
        const bf16* src;
        if (tile == 0)      src = Ah + (size_t)min(aRow0 + row, aMax) * 768 + k0 + ch * 8;
        else if (tile == 1) src = Al + (size_t)min(aRow0 + row, aMax) * 768 + k0 + ch * 8;
        else if (tile == 2) src = Bh + (size_t)(bRow0 + row) * 768 + k0 + ch * 8;
        else                src = Bl + (size_t)(bRow0 + row) * 768 + k0 + ch * 8;
        const uint32_t dst = sbase + buf * BUF_B + tile * TILE_B + row * 80 + ch * 16;
        CPA(dst, src);
    }
    CPA_COMMIT();
}

__device__ __forceinline__ void compute_stage(
    uint32_t sbase, int buf, int lane, int wid, float acc[4][4][4])
{
    const int wm = (wid >> 2) * 64;
    const int wn = (wid & 3) * 32;
    const uint32_t b0 = sbase + buf * BUF_B;
#pragma unroll
    for (int kk = 0; kk < 2; kk++) {
        uint32_t ah[4][4], al[4][4], bh[2][4], bl[2][4];
        const int ak = kk * 16 + ((lane >> 4) << 3);
        const int arow = wm + (lane & 15);
#pragma unroll
        for (int mi = 0; mi < 4; mi++) {
            const uint32_t off = (uint32_t)((arow + mi * 16) * 80 + ak * 2);
            ldsm4(ah[mi], b0 + off);
            ldsm4(al[mi], b0 + TILE_B + off);
        }
        const int bk = kk * 16 + (((lane >> 3) & 1) << 3);
        const int brow = wn + ((lane >> 4) << 3) + (lane & 7);
#pragma unroll
        for (int ni = 0; ni < 2; ni++) {
            const uint32_t off = (uint32_t)((brow + ni * 16) * 80 + bk * 2);
            ldsm4(bh[ni], b0 + 2 * TILE_B + off);
            ldsm4(bl[ni], b0 + 3 * TILE_B + off);
        }
#pragma unroll
        for (int mi = 0; mi < 4; mi++)
#pragma unroll
            for (int nj = 0; nj < 4; nj++) {
                const int ni = nj >> 1, rs = (nj & 1) * 2;
                uint32_t bH[2] = {bh[ni][rs], bh[ni][rs + 1]};
                uint32_t bL[2] = {bl[ni][rs], bl[ni][rs + 1]};
                mma_bf16(acc[mi][nj], ah[mi], bH);
                mma_bf16(acc[mi][nj], ah[mi], bL);
                mma_bf16(acc[mi][nj], al[mi], bH);
            }
    }
}

__device__ __forceinline__ void mma_mainloop(
    const bf16* Ah, const bf16* Al, const bf16* Bh, const bf16* Bl,
    int aRow0, int aMax, int bRow0, char* smem, float acc[4][4][4],
    int tid, int lane, int wid)
{
    const uint32_t sbase = smem_u32(smem);
    issue_stage(Ah, Al, Bh, Bl, aRow0, aMax, bRow0, sbase, 0, 0, tid);
#pragma unroll 1
    for (int s = 0; s < 24; s++) {
        CPA_WAIT(0);
        __syncthreads();
        if (s < 23)
            issue_stage(Ah, Al, Bh, Bl, aRow0, aMax, bRow0, sbase,
                        (s + 1) * 32, (s + 1) & 1, tid);
        compute_stage(sbase, s & 1, lane, wid, acc);
    }
}

// ============================================================================
// input conversions
// ============================================================================
__global__ void split_inputs_kernel(const float* __restrict__ et,
                                    const float* __restrict__ mt,
                                    const float* __restrict__ ec)
{
    const float* src; bf16 *hp, *lp; int n;
    switch (blockIdx.z) {
        case 0: src = et; hp = g_eth; lp = g_etl; n = MQ * DIN;  break;
        case 1: src = mt; hp = g_mth; lp = g_mtl; n = MKV * DIN; break;
        default: src = ec; hp = g_ech; lp = g_ecl; n = NA * DIN; break;
    }
    const int idx = (blockIdx.x * 256 + threadIdx.x) * 4;
    if (idx >= n) return;
    uint2 h, l;
    split4(*(const float4*)&src[idx], h, l);
    *(uint2*)&hp[idx] = h;
    *(uint2*)&lp[idx] = l;
}

__global__ void __launch_bounds__(256) wtrans_kernel(
    const float* __restrict__ Wq, const float* __restrict__ Wk,
    const float* __restrict__ Wv, const float* __restrict__ Wc)
{
    __shared__ float s[64][65];
    const float* W; bf16 *hp, *lp;
    switch (blockIdx.z) {
        case 0: W = Wq; hp = g_wqh; lp = g_wql; break;
        case 1: W = Wk; hp = g_wkh; lp = g_wkl; break;
        case 2: W = Wv; hp = g_wvh; lp = g_wvl; break;
        default: W = Wc; hp = g_wch; lp = g_wcl; break;
    }
    const int k0 = blockIdx.y * 64, n0 = blockIdx.x * 64;
    const int tid = threadIdx.x;
#pragma unroll
    for (int p = 0; p < 16; p++) {
        const int row = p * 4 + (tid >> 6), col = tid & 63;
        s[row][col] = W[(size_t)(k0 + row) * HD + n0 + col];
    }
    __syncthreads();
#pragma unroll
    for (int p = 0; p < 4; p++) {
        const int c = tid + p * 256;
        const int orow = c >> 4, oc = (c & 15) * 4;
        float4 v = make_float4(s[oc][orow], s[oc + 1][orow], s[oc + 2][orow], s[oc + 3][orow]);
        uint2 h, l;
        split4(v, h, l);
        const size_t o = (size_t)(n0 + orow) * HD + k0 + oc;
        *(uint2*)&hp[o] = h;
        *(uint2*)&lp[o] = l;
    }
}

// ============================================================================
// projections via mma.sync (fp32 out; v also written as bf16 hi/lo)
// ============================================================================
__global__ void __launch_bounds__(256) proj_mma_kernel(
    const float* __restrict__ bq, const float* __restrict__ bk,
    const float* __restrict__ bv, const float* __restrict__ bc)
{
    extern __shared__ char smem[];
    const bf16 *Ah, *Al, *Bh, *Bl; const float* bias; float* C; int m0, M;
    bool isV = false;
    const int y = blockIdx.y;
    if (y < 8)       { Ah = g_eth; Al = g_etl; Bh = g_wqh; Bl = g_wql; bias = bq; C = g_q;    m0 = y * 128;        M = MQ;  }
    else if (y < 24) { Ah = g_mth; Al = g_mtl; Bh = g_wkh; Bl = g_wkl; bias = bk; C = g_k;    m0 = (y - 8) * 128;  M = MKV; }
    else if (y < 40) { Ah = g_mth; Al = g_mtl; Bh = g_wvh; Bl = g_wvl; bias = bv; C = g_v;    m0 = (y - 24) * 128; M = MKV; isV = true; }
    else             { Ah = g_ech; Al = g_ecl; Bh = g_wch; Bl = g_wcl; bias = bc; C = g_ecls; m0 = 0;              M = NA;  }
    const int n0 = blockIdx.x * 128;
    const int tid = threadIdx.x, lane = tid & 31, wid = tid >> 5;

    float acc[4][4][4] = {};
    mma_mainloop(Ah, Al, Bh, Bl, m0, M - 1, n0, smem, acc, tid, lane, wid);

    const int wm = (wid >> 2) * 64, wn = (wid & 3) * 32;
#pragma unroll
    for (int mi = 0; mi < 4; mi++) {
        const int r0 = m0 + wm + mi * 16 + (lane >> 2);
#pragma unroll
        for (int nj = 0; nj < 4; nj++) {
            const int col = n0 + wn + nj * 8 + (lane & 3) * 2;
            const float b0 = bias[col], b1 = bias[col + 1];
            const float o00 = acc[mi][nj][0] + b0, o01 = acc[mi][nj][1] + b1;
            const float o10 = acc[mi][nj][2] + b0, o11 = acc[mi][nj][3] + b1;
            if (r0 < M)
                *(float2*)&C[(size_t)r0 * HD + col] = make_float2(o00, o01);
            if (r0 + 8 < M)
                *(float2*)&C[(size_t)(r0 + 8) * HD + col] = make_float2(o10, o11);
            if (isV) {
                uint32_t l0, l1;
                uint32_t h0 = split2(o00, o01, l0);
                uint32_t h1 = split2(o10, o11, l1);
                *(uint32_t*)&g_vh[(size_t)r0 * HD + col] = h0;
                *(uint32_t*)&g_vl[(size_t)r0 * HD + col] = l0;
                *(uint32_t*)&g_vh[(size_t)(r0 + 8) * HD + col] = h1;
                *(uint32_t*)&g_vl[(size_t)(r0 + 8) * HD + col] = l1;
            }
        }
    }
}

// ============================================================================
// NT GEMM: x<16: T = exp + fused sinkhorn -> g_Tp ; x>=16: M = q@v^T -> g_Mp
// ============================================================================
__global__ void __launch_bounds__(256) ntexp_ms_kernel()
{
    extern __shared__ char smem[];
    const int m0 = blockIdx.y * 128;
    const bool isK = blockIdx.x < 16;
    const int n0 = (isK ? blockIdx.x : (blockIdx.x - 16)) * 128;
    const int tid = threadIdx.x, lane = tid & 31, wid = tid >> 5;

    float acc[4][4][4] = {};
    if (isK)
        mma_mainloop(g_qh, g_ql, g_kh, g_kl, m0, MQ - 1, n0, smem, acc, tid, lane, wid);
    else
        mma_mainloop(g_qh, g_ql, g_vh, g_vl, m0, MQ - 1, n0, smem, acc, tid, lane, wid);

    const int wm = (wid >> 2) * 64, wn = (wid & 3) * 32;

    if (!isK) {
        // write M tile-packed
#pragma unroll
        for (int mi = 0; mi < 4; mi++) {
#pragma unroll
            for (int half = 0; half < 2; half++) {
                const int r = m0 + wm + mi * 16 + (lane >> 2) + half * 8;
                const int a = r >> 5, i = r & 31;
#pragma unroll
                for (int nj = 0; nj < 4; nj++) {
                    const int colv = n0 + wn + nj * 8 + (lane & 3) * 2;
                    const int bb = colv >> 5, j = colv & 31;
                    *(float2*)&g_Mp[(size_t)((a * 64 + bb) << 10) + (i << 5) + j] =
                        make_float2(acc[mi][nj][half * 2], acc[mi][nj][half * 2 + 1]);
                }
            }
        }
        return;
    }

    __syncthreads();   // mainloop smem dead; reuse
    float* st = (float*)smem;
#pragma unroll
    for (int mi = 0; mi < 4; mi++) {
        const int rr0 = wm + mi * 16 + (lane >> 2);
        const float ai0 = g_qinv[m0 + rr0] * OT_INV_EPS;
        const float ai1 = g_qinv[m0 + rr0 + 8] * OT_INV_EPS;
#pragma unroll
        for (int nj = 0; nj < 4; nj++) {
            const int cl = wn + nj * 8 + (lane & 3) * 2;
            const float b0 = g_kinv[n0 + cl], b1 = g_kinv[n0 + cl + 1];
            const int tj = cl >> 5, j = cl & 31;
            {
                const int ti = rr0 >> 5, i = rr0 & 31;
                float* p = st + (ti * 4 + tj) * 1056 + i * 33 + j;
                p[0] = __expf(acc[mi][nj][0] * ai0 * b0);
                p[1] = __expf(acc[mi][nj][1] * ai0 * b1);
            }
            {
                const int rr1 = rr0 + 8;
                const int ti = rr1 >> 5, i = rr1 & 31;
                float* p = st + (ti * 4 + tj) * 1056 + i * 33 + j;
                p[0] = __expf(acc[mi][nj][2] * ai1 * b0);
                p[1] = __expf(acc[mi][nj][3] * ai1 * b1);
            }
        }
    }
    __syncthreads();

#pragma unroll 1
    for (int tt = 0; tt < 2; tt++) {
        const int t = wid + tt * 8;
        const int ti = t >> 2, tj = t & 3;
        const float* S = st + t * 1056;
        float Q[32], QT[32];
#pragma unroll
        for (int j = 0; j < 32; j++) Q[j]  = S[lane * 33 + j];
#pragma unroll
        for (int j = 0; j < 32; j++) QT[j] = S[j * 33 + lane];
        float v_all[32];
#pragma unroll
        for (int j = 0; j < 32; j++) v_all[j] = 1.0f;
#pragma unroll 1
        for (int it = 0; it < 10; it++) {
            float s = 0.f;
#pragma unroll
            for (int j = 0; j < 32; j++) s = fmaf(Q[j], v_all[j], s);
            const float u = __fdividef(1.0f, s);
#pragma unroll
            for (int j = 0; j < 32; j++) v_all[j] = __shfl_sync(0xffffffffu, u, j);
            float s2 = 0.f;
#pragma unroll
            for (int j = 0; j < 32; j++) s2 = fmaf(QT[j], v_all[j], s2);
            const float v = __fdividef(1.0f, s2);
#pragma unroll
            for (int j = 0; j < 32; j++) v_all[j] = __shfl_sync(0xffffffffu, v, j);
        }
        float n2 = 0.f;
#pragma unroll
        for (int j = 0; j < 32; j++) {
            Q[j] *= v_all[j];
            n2 = fmaf(Q[j], Q[j], n2);
        }
        const float sc = __fdividef(1.0f, fmaxf(sqrtf(n2), 1e-12f));
        const int tileg = (m0 / 32 + ti) * 64 + (n0 / 32 + tj);
        float* dst = g_Tp + (size_t)tileg * 1024 + lane * 32;
#pragma unroll
        for (int p = 0; p < 8; p++)
            *(float4*)&dst[p * 4] = make_float4(Q[p*4] * sc, Q[p*4+1] * sc,
                                                Q[p*4+2] * sc, Q[p*4+3] * sc);
    }
}

// ============================================================================
// row L2-norm inverse + bf16 hi/lo of q,k + q row stats (qsum, qsq, qwsp)
// ============================================================================
__global__ void rownorm_convert_kernel(const float* __restrict__ Wsp,
                                       const float* __restrict__ ln1g)
{
    int row = blockIdx.x * 8 + (threadIdx.x >> 5);
    int lane = threadIdx.x & 31;
    const float* x; float* inv; bf16 *hp, *lp;
    const bool isQ = row < MQ;
    if (isQ) {
        x = g_q + (size_t)row * HD; inv = g_qinv + row;
        hp = g_qh + (size_t)row * HD; lp = g_ql + (size_t)row * HD;
    } else {
        int r2 = row - MQ;
        x = g_k + (size_t)r2 * HD; inv = g_kinv + r2;
        hp = g_kh + (size_t)r2 * HD; lp = g_kl + (size_t)r2 * HD;
    }
    float s = 0.f, s0 = 0.f, s2 = 0.f;
#pragma unroll
    for (int p = 0; p < 6; p++) {
        const int d = lane * 4 + p * 128;
        float4 v4 = *(const float4*)&x[d];
        s += v4.x * v4.x + v4.y * v4.y + v4.z * v4.z + v4.w * v4.w;
        if (isQ) {
            float4 w4 = *(const float4*)&Wsp[d];
            float4 g4 = *(const float4*)&ln1g[d];
            s0 += v4.x + v4.y + v4.z + v4.w;
            s2 += v4.x * g4.x * w4.x + v4.y * g4.y * w4.y
                + v4.z * g4.z * w4.z + v4.w * g4.w * w4.w;
        }
        uint2 h, l;
        split4(v4, h, l);
        *(uint2*)&hp[d] = h;
        *(uint2*)&lp[d] = l;
    }
    s = warp_sum(s);
    if (isQ) { s0 = warp_sum(s0); s2 = warp_sum(s2); }
    if (lane == 0) {
        *inv = 1.0f / fmaxf(sqrtf(s), 1e-8f);
        if (isQ) { g_qsum[row] = s0; g_qsq[row] = s; g_qwsp[row] = s2; }
    }
}

// ============================================================================
// Gram kernel: per b: G = v_b v_b^T, vsum, vwsp'; block 0 also S1
// ============================================================================
__global__ void __launch_bounds__(256) gram_kernel(const float* __restrict__ Wsp,
                                                   const float* __restrict__ ln1g)
{
    extern __shared__ float sv[];   // 32 rows x 772 stride
    const int b = blockIdx.x;
    const int tid = threadIdx.x;
    for (int t = tid; t < 6144; t += 256) {
        const int row = t / 192, c4 = (t % 192) * 4;
        *(float4*)&sv[row * 772 + c4] = *(const float4*)&g_v[(size_t)(b * 32 + row) * HD + c4];
    }
    __syncthreads();

    // 2x2 G tiles per thread
    const int j0 = (tid >> 4) * 2, k0 = (tid & 15) * 2;
    float a00 = 0, a01 = 0, a10 = 0, a11 = 0;
    for (int d = 0; d < 768; d += 4) {
        float4 vj0 = *(const float4*)&sv[j0 * 772 + d];
        float4 vj1 = *(const float4*)&sv[(j0 + 1) * 772 + d];
        float4 vk0 = *(const float4*)&sv[k0 * 772 + d];
        float4 vk1 = *(const float4*)&sv[(k0 + 1) * 772 + d];
        a00 += vj0.x*vk0.x + vj0.y*vk0.y + vj0.z*vk0.z + vj0.w*vk0.w;
        a01 += vj0.x*vk1.x + vj0.y*vk1.y + vj0.z*vk1.z + vj0.w*vk1.w;
        a10 += vj1.x*vk0.x + vj1.y*vk0.y + vj1.z*vk0.z + vj1.w*vk0.w;
        a11 += vj1.x*vk1.x + vj1.y*vk1.y + vj1.z*vk1.z + vj1.w*vk1.w;
    }
    float* Gb = g_G + b * 1024;
    Gb[j0 * 32 + k0] = a00;       Gb[j0 * 32 + k0 + 1] = a01;
    Gb[(j0+1) * 32 + k0] = a10;   Gb[(j0+1) * 32 + k0 + 1] = a11;

    // vsum / vwsp per row
    const int w = tid >> 5, lane = tid & 31;
    for (int r = w; r < 32; r += 8) {
        float s1 = 0.f, s2 = 0.f;
#pragma unroll
        for (int p = 0; p < 6; p++) {
            const int d = lane * 4 + p * 128;
            float4 vv = *(const float4*)&sv[r * 772 + d];
            float4 w4 = *(const float4*)&Wsp[d];
            float4 g4 = *(const float4*)&ln1g[d];
            s1 += vv.x + vv.y + vv.z + vv.w;
            s2 += vv.x*g4.x*w4.x + vv.y*g4.y*w4.y + vv.z*g4.z*w4.z + vv.w*g4.w*w4.w;
        }
        s1 = warp_sum(s1); s2 = warp_sum(s2);
        if (lane == 0) { g_vsum[b * 32 + r] = s1; g_vwsp[b * 32 + r] = s2; }
    }
    if (b == 0 && w == 0) {
        float s1 = 0.f;
#pragma unroll
        for (int p = 0; p < 6; p++) {
            const int d = lane * 4 + p * 128;
            float4 w4 = *(const float4*)&Wsp[d];
            float4 g4 = *(const float4*)&ln1g[d];
            s1 += g4.x*w4.x + g4.y*w4.y + g4.z*w4.z + g4.w*w4.w;
        }
        s1 = warp_sum(s1);
        if (lane == 0) g_S1 = s1;
    }
}

// ============================================================================
// Stage A: warp per (a,b): all LN1/softpool stats from 32-dim algebra
// ============================================================================
__global__ void __launch_bounds__(256) stageA_kernel()
{
    __shared__ float sG[32 * 33];
    __shared__ float svs[32], svw[32];
    __shared__ float ssc[8][32 * 36];
    __shared__ float sS1;
    const int tid = threadIdx.x, lane = tid & 31, w = tid >> 5;
    const int b = blockIdx.x;
    const int a = blockIdx.y * 8 + w;
    const int pair = a * 64 + b;

    for (int t = tid; t < 1024; t += 256)
        sG[(t >> 5) * 33 + (t & 31)] = g_G[b * 1024 + t];
    if (tid < 32) { svs[tid] = g_vsum[b * 32 + tid]; svw[tid] = g_vwsp[b * 32 + tid]; }
    if (tid == 64) sS1 = g_S1;
    __syncthreads();

    float T[32], M[32];
    {
        const float* Tb = g_Tp + (size_t)pair * 1024 + lane * 32;
        const float* Mb = g_Mp + (size_t)pair * 1024 + lane * 32;
#pragma unroll
        for (int p = 0; p < 8; p++) {
            float4 t4 = *(const float4*)&Tb[p * 4];
            T[p*4] = t4.x; T[p*4+1] = t4.y; T[p*4+2] = t4.z; T[p*4+3] = t4.w;
            float4 m4 = *(const float4*)&Mb[p * 4];
            M[p*4] = m4.x; M[p*4+1] = m4.y; M[p*4+2] = m4.z; M[p*4+3] = m4.w;
        }
    }
    float tgt = 0.f, tv = 0.f, xw = 0.f, tm = 0.f;
#pragma unroll 4
    for (int j = 0; j < 32; j++) {
        const float tj = T[j];
        float sj = 0.f;
#pragma unroll
        for (int k = 0; k < 32; k++) sj = fmaf(sG[j * 33 + k], T[k], sj);
        tgt = fmaf(tj, sj, tgt);
        tv  = fmaf(tj, svs[j], tv);
        xw  = fmaf(tj, svw[j], xw);
        tm  = fmaf(tj, M[j], tm);
    }
    const int row = a * 32 + lane;
    const float mean = (tv + g_qsum[row]) * INV768;
    const float xws = xw + g_qwsp[row];
    const float sumsq = tgt + 2.0f * tm + g_qsq[row];
    const float var = sumsq * INV768 - mean * mean;
    const float rstd = rsqrtf(var + 1e-5f);
    const float score = rstd * (xws - mean * sS1);

    const float mx = warp_max(score);
    const float e = __expf(score - mx);
    const float se = warp_sum(e);
    const float wgt = e / se;
    const float wr = wgt * rstd;
    const float Kp = warp_sum(wr * mean);

    float* S = ssc[w];
#pragma unroll
    for (int p = 0; p < 8; p++)
        *(float4*)&S[lane * 36 + p * 4] =
            make_float4(wr * T[p*4], wr * T[p*4+1], wr * T[p*4+2], wr * T[p*4+3]);
    __syncwarp();
    float c = 0.f;
#pragma unroll
    for (int i = 0; i < 32; i++) c += S[i * 36 + lane];

    g_WR[pair * 32 + lane] = wr;
    g_C[pair * 32 + lane] = c;
    if (lane == 0) g_K[pair] = Kp;
}

// ============================================================================
// B1: R[a,b,:] = sum_j c_j v_b[j,:]   grid (64 b, 6 dchunk)
// ============================================================================
__global__ void __launch_bounds__(256) poolB1_kernel()
{
    __shared__ float sv[32 * 128];
    __shared__ float sc[32 * 32];
    const int b = blockIdx.x, dc = blockIdx.y;
    const int tid = threadIdx.x;
#pragma unroll
    for (int tt = 0; tt < 4; tt++) {
        const int idx = tid + tt * 256;           // 0..1023 float4 units
        const int row = idx >> 5, c4 = (idx & 31) * 4;
        *(float4*)&sv[row * 128 + c4] =
            *(const float4*)&g_v[(size_t)(b * 32 + row) * HD + dc * 128 + c4];
    }
    {
        const int aa = tid >> 3, j4 = (tid & 7) * 4;
        *(float4*)&sc[aa * 32 + j4] = *(const float4*)&g_C[(aa * 64 + b) * 32 + j4];
    }
    __syncthreads();

    const int a = tid >> 3, dd = (tid & 7) * 16;
    float acc[16] = {};
#pragma unroll
    for (int j = 0; j < 32; j++) {
        const float cv = sc[a * 32 + j];
        const float4 v0 = *(const float4*)&sv[j * 128 + dd];
        const float4 v1 = *(const float4*)&sv[j * 128 + dd + 4];
        const float4 v2 = *(const float4*)&sv[j * 128 + dd + 8];
        const float4 v3 = *(const float4*)&sv[j * 128 + dd + 12];
        acc[0]  = fmaf(cv, v0.x, acc[0]);  acc[1]  = fmaf(cv, v0.y, acc[1]);
        acc[2]  = fmaf(cv, v0.z, acc[2]);  acc[3]  = fmaf(cv, v0.w, acc[3]);
        acc[4]  = fmaf(cv, v1.x, acc[4]);  acc[5]  = fmaf(cv, v1.y, acc[5]);
        acc[6]  = fmaf(cv, v1.z, acc[6]);  acc[7]  = fmaf(cv, v1.w, acc[7]);
        acc[8]  = fmaf(cv, v2.x, acc[8]);  acc[9]  = fmaf(cv, v2.y, acc[9]);
        acc[10] = fmaf(cv, v2.z, acc[10]); acc[11] = fmaf(cv, v2.w, acc[11]);
        acc[12] = fmaf(cv, v3.x, acc[12]); acc[13] = fmaf(cv, v3.y, acc[13]);
        acc[14] = fmaf(cv, v3.z, acc[14]); acc[15] = fmaf(cv, v3.w, acc[15]);
    }
    float* dst = g_R + (size_t)(a * 64 + b) * HD + dc * 128 + dd;
#pragma unroll
    for (int p = 0; p < 4; p++)
        *(float4*)&dst[p * 4] = make_float4(acc[p*4], acc[p*4+1], acc[p*4+2], acc[p*4+3]);
}

// ============================================================================
// B2: R[a,b,:] += sum_i wr_i q_a[i,:]   grid (32 a, 6 dchunk)
// ============================================================================
__global__ void __launch_bounds__(256) poolB2_kernel()
{
    __shared__ float sq[32 * 128];
    __shared__ float swr[64 * 32];
    const int a = blockIdx.x, dc = blockIdx.y;
    const int tid = threadIdx.x;
#pragma unroll
    for (int tt = 0; tt < 4; tt++) {
        const int idx = tid + tt * 256;
        const int row = idx >> 5, c4 = (idx & 31) * 4;
        *(float4*)&sq[row * 128 + c4] =
            *(const float4*)&g_q[(size_t)(a * 32 + row) * HD + dc * 128 + c4];
    }
#pragma unroll
    for (int tt = 0; tt < 2; tt++) {
        const int id = tid + tt * 256;            // 0..511
        const int bb = id >> 3, i4 = (id & 7) * 4;
        *(float4*)&swr[bb * 32 + i4] = *(const float4*)&g_WR[(a * 64 + bb) * 32 + i4];
    }
    __syncthreads();

    const int bb = tid >> 2, dg = (tid & 3) * 32;
    float acc[32] = {};
#pragma unroll 8
    for (int i = 0; i < 32; i++) {
        const float wv = swr[bb * 32 + i];
#pragma unroll
        for (int p = 0; p < 8; p++) {
            const float4 qv = *(const float4*)&sq[i * 128 + dg + p * 4];
            acc[p*4]   = fmaf(wv, qv.x, acc[p*4]);
            acc[p*4+1] = fmaf(wv, qv.y, acc[p*4+1]);
            acc[p*4+2] = fmaf(wv, qv.z, acc[p*4+2]);
            acc[p*4+3] = fmaf(wv, qv.w, acc[p*4+3]);
        }
    }
    float* dst = g_R + (size_t)(a * 64 + bb) * HD + dc * 128 + dg;
#pragma unroll
    for (int p = 0; p < 8; p++) {
        float4 r = *(const float4*)&dst[p * 4];
        r.x += acc[p*4]; r.y += acc[p*4+1]; r.z += acc[p*4+2]; r.w += acc[p*4+3];
        *(float4*)&dst[p * 4] = r;
    }
}

// ============================================================================
// Stage C: warp per pair: pooled = g(R-K)+lb ; LN2 ; g2l, g2g ; output
// ============================================================================
__global__ void __launch_bounds__(256) stageC_kernel(
    const float* __restrict__ ln1g, const float* __restrict__ ln1b,
    const float* __restrict__ ln2g, const float* __restrict__ ln2b,
    const float* __restrict__ entity_cls, const float* __restrict__ mention_cls,
    float* __restrict__ out)
{
    const int tid = threadIdx.x, lane = tid & 31, w = tid >> 5;
    const int pair = blockIdx.x * 8 + w;
    const int a = pair >> 6, b = pair & 63;
    const float K = g_K[pair];

    float p[24];
    float s = 0.f, sq = 0.f;
#pragma unroll
    for (int pp = 0; pp < 6; pp++) {
        const int d = lane * 4 + pp * 128;
        float4 r  = *(const float4*)&g_R[(size_t)pair * HD + d];
        float4 g4 = *(const float4*)&ln1g[d];
        float4 b4 = *(const float4*)&ln1b[d];
        float4 y;
        y.x = g4.x * (r.x - K) + b4.x;
        y.y = g4.y * (r.y - K) + b4.y;
        y.z = g4.z * (r.z - K) + b4.z;
        y.w = g4.w * (r.w - K) + b4.w;
        p[pp*4] = y.x; p[pp*4+1] = y.y; p[pp*4+2] = y.z; p[pp*4+3] = y.w;
        s += y.x + y.y + y.z + y.w;
        sq += y.x*y.x + y.y*y.y + y.z*y.z + y.w*y.w;
    }
    s = warp_sum(s); sq = warp_sum(sq);
    const float mean2 = s * INV768;
    const float var2 = sq * INV768 - mean2 * mean2;
    const float rstd2 = rsqrtf(var2 + 1e-5f);

    float g2l = 0.f, g2g = 0.f;
#pragma unroll
    for (int pp = 0; pp < 6; pp++) {
        const int d = lane * 4 + pp * 128;
        float4 g4 = *(const float4*)&ln2g[d];
        float4 b4 = *(const float4*)&ln2b[d];
        float4 e4 = *(const float4*)&g_ecls[(size_t)a * HD + d];
        float4 mc = *(const float4*)&mention_cls[(size_t)b * HD + d];
        float4 ec = *(const float4*)&entity_cls[(size_t)a * HD + d];
        float c0 = (p[pp*4]   - mean2) * rstd2 * g4.x + b4.x;
        float c1 = (p[pp*4+1] - mean2) * rstd2 * g4.y + b4.y;
        float c2 = (p[pp*4+2] - mean2) * rstd2 * g4.z + b4.z;
        float c3 = (p[pp*4+3] - mean2) * rstd2 * g4.w + b4.w;
        g2l += e4.x*c0 + e4.y*c1 + e4.z*c2 + e4.w*c3;
        g2g += mc.x*ec.x + mc.y*ec.y + mc.z*ec.z + mc.w*ec.w;
    }
    g2l = warp_sum(g2l); g2g = warp_sum(g2g);
    if (lane == 0) out[b * NA + a] = 0.5f * (g2l + g2g);
}

// ---------------------------------------------------------------------------
extern "C" void kernel_launch(void* const* d_in, const int* in_sizes, int n_in,
                              void* d_out, int out_size)
{
    const float* entity_cls     = (const float*)d_in[0];
    const float* entity_tokens  = (const float*)d_in[1];
    const float* mention_cls    = (const float*)d_in[2];
    const float* mention_tokens = (const float*)d_in[3];
    const float* Wq   = (const float*)d_in[4];
    const float* bq   = (const float*)d_in[5];
    const float* Wk   = (const float*)d_in[6];
    const float* bk   = (const float*)d_in[7];
    const float* Wv   = (const float*)d_in[8];
    const float* bv   = (const float*)d_in[9];
    const float* ln1g = (const float*)d_in[10];
    const float* ln1b = (const float*)d_in[11];
    const float* Wcls = (const float*)d_in[12];
    const float* bcls = (const float*)d_in[13];
    const float* Wsp  = (const float*)d_in[14];
    const float* ln2g = (const float*)d_in[16];
    const float* ln2b = (const float*)d_in[17];
    float* out = (float*)d_out;

    split_inputs_kernel<<<dim3(1536, 1, 3), 256>>>(entity_tokens, mention_tokens, entity_cls);
    wtrans_kernel<<<dim3(12, 12, 4), 256>>>(Wq, Wk, Wv, Wcls);

    cudaFuncSetAttribute(proj_mma_kernel, cudaFuncAttributeMaxDynamicSharedMemorySize, SMEM_MMA);
    proj_mma_kernel<<<dim3(6, 41), 256, SMEM_MMA>>>(bq, bk, bv, bcls);

    rownorm_convert_kernel<<<(MQ + MKV) / 8, 256>>>(Wsp, ln1g);

    const int gram_smem = 32 * 772 * 4;
    cudaFuncSetAttribute(gram_kernel, cudaFuncAttributeMaxDynamicSharedMemorySize, gram_smem);
    gram_kernel<<<64, 256, gram_smem>>>(Wsp, ln1g);

    cudaFuncSetAttribute(ntexp_ms_kernel, cudaFuncAttributeMaxDynamicSharedMemorySize, SMEM_MMA);
    ntexp_ms_kernel<<<dim3(32, 8), 256, SMEM_MMA>>>();

    stageA_kernel<<<dim3(64, 4), 256>>>();
    poolB1_kernel<<<dim3(64, 6), 256>>>();
    poolB2_kernel<<<dim3(32, 6), 256>>>();
    stageC_kernel<<<256, 256>>>(ln1g, ln1b, ln2g, ln2b, entity_cls, mention_cls, out);
}